// round 12
// baseline (speedup 1.0000x reference)
#include <cuda_runtime.h>

// ButterflyLinear: 12 butterfly stages on N=4096, TOKENS=8192.
// Stage 0 pairs (j, j^1); stages 1..11 all pair (j, j^2) => transform is
// block-diagonal in 4-element groups: out = blockdiag(A_g) * x + bias.
//
// SINGLE kernel, cheap soft barrier (R9 retry with the atomics fixed):
//  - fold duty by blockIdx (bids 0..15 are wave-1 resident; NO global
//    ticket atomic -> removes ~2us of serialized L2 RMW);
//  - finish/reset counting is hierarchical over 64 L2 addresses (removes
//    another ~2us of single-address RMW serialization);
//  - streaming body = R11's MLP_p1=8 form (36.96us / 72.9% DRAM standalone);
//  - no pre-barrier prefetch (R10 showed it contends with the fold's loads).

#define TOKENS 8192
#define NCOLS  4096
#define DEPTH  12
#define GROUPS (NCOLS / 4)   // 1024
#define PAIRS  (NCOLS / 2)   // 2048 factor pairs per stage
#define T_PER  8             // tokens per thread -> 4096 blocks
#define FOLD_BLOCKS 16       // 16 blocks x 256 threads = 4096 fold tasks
#define FIN_SLOTS 64         // 4096 blocks / 64 slots = 64 per slot

// g_C[g*4+e] = column e of A_g = (A[0][e], A[1][e], A[2][e], A[3][e]); 64KB.
__device__ float4   g_C[GROUPS * 4];
__device__ unsigned g_folddone = 0;
__device__ unsigned g_fin[FIN_SLOTS];
__device__ unsigned g_fin2 = 0;

// ---------------------------------------------------------------------------
// Fold one (group, column) task. Column-separable recurrence; factor loads
// batched 6 stages at a time (12 float4 live -> 2 DRAM round-trips total).
// factors: F[stage][pair] as float4 (f.x=f[0][0], f.y=f[0][1], f.z=f[1][0],
// f.w=f[1][1]); stage semantics y[d] = sum_c in[c]*f[c][d].
// ---------------------------------------------------------------------------
__device__ __forceinline__ void fold_task(int idx, const float4* __restrict__ F4) {
    int g = idx >> 2;
    int e = idx & 3;
    int j0 = 4 * g;

    float A0, A1, A2, A3;
    {
        float4 f0 = F4[2 * g];
        float4 f1 = F4[2 * g + 1];
        bool lo = (e < 2);
        float4 f = lo ? f0 : f1;
        float u = (e & 1) ? f.z : f.x;
        float v = (e & 1) ? f.w : f.y;
        A0 = lo ? u : 0.f;
        A1 = lo ? v : 0.f;
        A2 = lo ? 0.f : u;
        A3 = lo ? 0.f : v;
    }

    #pragma unroll
    for (int c0 = 1; c0 < DEPTH; c0 += 6) {
        float4 fa[6], fb[6];
        #pragma unroll
        for (int k = 0; k < 6; k++) {
            int s = c0 + k;
            if (s < DEPTH) {
                int block = 1 << (s + 1);
                int pA = ((j0 >> (s + 1)) << s) | ((j0 & (block - 1)) >> 2);
                int pB = pA + (1 << (s - 1));
                fa[k] = F4[s * PAIRS + pA];
                fb[k] = F4[s * PAIRS + pB];
            }
        }
        #pragma unroll
        for (int k = 0; k < 6; k++) {
            int s = c0 + k;
            if (s < DEPTH) {
                float r0 = A0, r1 = A1, r2 = A2, r3 = A3;
                A0 = fa[k].x * r0 + fa[k].z * r2;
                A2 = fa[k].y * r0 + fa[k].w * r2;
                A1 = fb[k].x * r1 + fb[k].z * r3;
                A3 = fb[k].y * r1 + fb[k].w * r3;
            }
        }
    }

    g_C[idx] = make_float4(A0, A1, A2, A3);
}

// ---------------------------------------------------------------------------
__global__ void __launch_bounds__(256, 4)
butterfly_one(const float4* __restrict__ F4,
              const float4* __restrict__ x,
              const float4* __restrict__ bias4,
              float4* __restrict__ out) {
    unsigned bid = blockIdx.y * gridDim.x + blockIdx.x;

    // ---- fold duty: bids 0..15 (wave-1 resident by construction) ----
    if (bid < FOLD_BLOCKS) {
        fold_task((int)(bid * 256 + threadIdx.x), F4);
        __threadfence();                 // release g_C writes
        __syncthreads();                 // all 256 fold lanes done
        if (threadIdx.x == 0) atomicAdd(&g_folddone, 1u);
    }

    // ---- wait for fold completion (volatile polls; no RMW serialization) ----
    if (threadIdx.x == 0) {
        while (*(volatile unsigned*)&g_folddone < FOLD_BLOCKS) __nanosleep(128);
    }
    __syncthreads();
    __threadfence();                     // acquire g_C

    // ---- streaming phase: exact R11 body (MLP_p1 = 8) ----
    int g  = blockIdx.x * blockDim.x + threadIdx.x;  // 0..GROUPS-1
    int t0 = blockIdx.y * T_PER;

    const float4* xp = x   + (size_t)t0 * GROUPS + g;
    float4*       op = out + (size_t)t0 * GROUPS + g;

    float4 v0 = __ldcs(xp + 0 * GROUPS);
    float4 v1 = __ldcs(xp + 1 * GROUPS);
    float4 v2 = __ldcs(xp + 2 * GROUPS);
    float4 v3 = __ldcs(xp + 3 * GROUPS);
    float4 v4 = __ldcs(xp + 4 * GROUPS);
    float4 v5 = __ldcs(xp + 5 * GROUPS);
    float4 v6 = __ldcs(xp + 6 * GROUPS);
    float4 v7 = __ldcs(xp + 7 * GROUPS);

    float4 c0 = g_C[g * 4 + 0];
    float4 c1 = g_C[g * 4 + 1];
    float4 c2 = g_C[g * 4 + 2];
    float4 c3 = g_C[g * 4 + 3];
    float4 b  = bias4[g];

    float4 r0, r1, r2, r3;
    r0.x = b.x + v0.x*c0.x + v0.y*c1.x + v0.z*c2.x + v0.w*c3.x;
    r0.y = b.y + v0.x*c0.y + v0.y*c1.y + v0.z*c2.y + v0.w*c3.y;
    r0.z = b.z + v0.x*c0.z + v0.y*c1.z + v0.z*c2.z + v0.w*c3.z;
    r0.w = b.w + v0.x*c0.w + v0.y*c1.w + v0.z*c2.w + v0.w*c3.w;

    r1.x = b.x + v1.x*c0.x + v1.y*c1.x + v1.z*c2.x + v1.w*c3.x;
    r1.y = b.y + v1.x*c0.y + v1.y*c1.y + v1.z*c2.y + v1.w*c3.y;
    r1.z = b.z + v1.x*c0.z + v1.y*c1.z + v1.z*c2.z + v1.w*c3.z;
    r1.w = b.w + v1.x*c0.w + v1.y*c1.w + v1.z*c2.w + v1.w*c3.w;

    r2.x = b.x + v2.x*c0.x + v2.y*c1.x + v2.z*c2.x + v2.w*c3.x;
    r2.y = b.y + v2.x*c0.y + v2.y*c1.y + v2.z*c2.y + v2.w*c3.y;
    r2.z = b.z + v2.x*c0.z + v2.y*c1.z + v2.z*c2.z + v2.w*c3.z;
    r2.w = b.w + v2.x*c0.w + v2.y*c1.w + v2.z*c2.w + v2.w*c3.w;

    r3.x = b.x + v3.x*c0.x + v3.y*c1.x + v3.z*c2.x + v3.w*c3.x;
    r3.y = b.y + v3.x*c0.y + v3.y*c1.y + v3.z*c2.y + v3.w*c3.y;
    r3.z = b.z + v3.x*c0.z + v3.y*c1.z + v3.z*c2.z + v3.w*c3.z;
    r3.w = b.w + v3.x*c0.w + v3.y*c1.w + v3.z*c2.w + v3.w*c3.w;

    __stcs(op + 0 * GROUPS, r0);
    __stcs(op + 1 * GROUPS, r1);
    __stcs(op + 2 * GROUPS, r2);
    __stcs(op + 3 * GROUPS, r3);

    r0.x = b.x + v4.x*c0.x + v4.y*c1.x + v4.z*c2.x + v4.w*c3.x;
    r0.y = b.y + v4.x*c0.y + v4.y*c1.y + v4.z*c2.y + v4.w*c3.y;
    r0.z = b.z + v4.x*c0.z + v4.y*c1.z + v4.z*c2.z + v4.w*c3.z;
    r0.w = b.w + v4.x*c0.w + v4.y*c1.w + v4.z*c2.w + v4.w*c3.w;

    r1.x = b.x + v5.x*c0.x + v5.y*c1.x + v5.z*c2.x + v5.w*c3.x;
    r1.y = b.y + v5.x*c0.y + v5.y*c1.y + v5.z*c2.y + v5.w*c3.y;
    r1.z = b.z + v5.x*c0.z + v5.y*c1.z + v5.z*c2.z + v5.w*c3.z;
    r1.w = b.w + v5.x*c0.w + v5.y*c1.w + v5.z*c2.w + v5.w*c3.w;

    r2.x = b.x + v6.x*c0.x + v6.y*c1.x + v6.z*c2.x + v6.w*c3.x;
    r2.y = b.y + v6.x*c0.y + v6.y*c1.y + v6.z*c2.y + v6.w*c3.y;
    r2.z = b.z + v6.x*c0.z + v6.y*c1.z + v6.z*c2.z + v6.w*c3.z;
    r2.w = b.w + v6.x*c0.w + v6.y*c1.w + v6.z*c2.w + v6.w*c3.w;

    r3.x = b.x + v7.x*c0.x + v7.y*c1.x + v7.z*c2.x + v7.w*c3.x;
    r3.y = b.y + v7.x*c0.y + v7.y*c1.y + v7.z*c2.y + v7.w*c3.y;
    r3.z = b.z + v7.x*c0.z + v7.y*c1.z + v7.z*c2.z + v7.w*c3.z;
    r3.w = b.w + v7.x*c0.w + v7.y*c1.w + v7.z*c2.w + v7.w*c3.w;

    __stcs(op + 4 * GROUPS, r0);
    __stcs(op + 5 * GROUPS, r1);
    __stcs(op + 6 * GROUPS, r2);
    __stcs(op + 7 * GROUPS, r3);

    // ---- hierarchical finish counting; last block resets all flags ----
    if (threadIdx.x == 0) {
        __threadfence();
        unsigned slot = bid & (FIN_SLOTS - 1);
        unsigned o = atomicAdd(&g_fin[slot], 1u);      // 64 blocks per slot
        if (o == 63u) {
            unsigned o2 = atomicAdd(&g_fin2, 1u);      // 64 slot-finishers
            if (o2 == (unsigned)(FIN_SLOTS - 1)) {
                g_folddone = 0;
                #pragma unroll
                for (int i = 0; i < FIN_SLOTS; i++) g_fin[i] = 0;
                g_fin2 = 0;
                __threadfence();
            }
        }
    }
}

// ---------------------------------------------------------------------------
extern "C" void kernel_launch(void* const* d_in, const int* in_sizes, int n_in,
                              void* d_out, int out_size) {
    const float* x = nullptr;
    const float* factors = nullptr;
    const float* bias = nullptr;
    for (int i = 0; i < n_in; i++) {
        if (in_sizes[i] == TOKENS * NCOLS)            x = (const float*)d_in[i];
        else if (in_sizes[i] == DEPTH * PAIRS * 4)    factors = (const float*)d_in[i];
        else if (in_sizes[i] == NCOLS)                bias = (const float*)d_in[i];
    }

    dim3 grid(GROUPS / 256, TOKENS / T_PER);   // (4, 1024) = 4096 blocks
    butterfly_one<<<grid, 256>>>((const float4*)factors,
                                 (const float4*)x,
                                 (const float4*)bias,
                                 (float4*)d_out);
}

// round 13
// speedup vs baseline: 1.0109x; 1.0109x over previous
#include <cuda_runtime.h>

// ButterflyLinear: 12 butterfly stages on N=4096, TOKENS=8192.
// Stage 0 pairs (j, j^1); stages 1..11 all pair (j, j^2) => transform is
// block-diagonal in 4-element groups. Kernel 1 folds per-group 4x4s
// (column-parallel, 4096 threads). Kernel 2 streams out = blockdiag(A)*x + b.
// R13 change: apply front-batches ALL 16 token loads (MLP_p1 = 16) under a
// 128-reg cap (2 CTA/SM). R11 proved MLP_p1 is the only lever that moves
// the streaming rate; occupancy 63%->39% was free, now test 39%->25%.

#define TOKENS 8192
#define NCOLS  4096
#define DEPTH  12
#define GROUPS (NCOLS / 4)   // 1024
#define PAIRS  (NCOLS / 2)   // 2048 factor pairs per stage
#define T_PER  16            // tokens per thread -> 2048 blocks

// Scratch: 1024 groups x 4 columns (each column = float4) = 64 KB.
// g_C[g*4+e] = (A[0][e], A[1][e], A[2][e], A[3][e])
__device__ float4 g_C[GROUPS * 4];

// ---------------------------------------------------------------------------
// Kernel 1: one thread per (group, column); column-separable fold with
// front-batched MLP=24 loads (one DRAM round-trip).
// factors layout: F[stage][pair][c][d] as float4 per pair:
//   f.x=f[0][0], f.y=f[0][1], f.z=f[1][0], f.w=f[1][1]
// Stage semantics: y[d] = sum_c pair_in[c] * f[c][d]
// ---------------------------------------------------------------------------
__global__ void butterfly_precompute(const float4* __restrict__ F4) {
    int t = blockIdx.x * blockDim.x + threadIdx.x;   // 0..4095
    int g = t >> 2;
    int e = t & 3;
    int j0 = 4 * g;

    float4 fa[DEPTH], fb[DEPTH];
    fa[0] = F4[2 * g];
    fb[0] = F4[2 * g + 1];
    #pragma unroll
    for (int s = 1; s < DEPTH; s++) {
        int block = 1 << (s + 1);
        int pA = ((j0 >> (s + 1)) << s) | ((j0 & (block - 1)) >> 2);
        int pB = pA + (1 << (s - 1));
        fa[s] = F4[s * PAIRS + pA];
        fb[s] = F4[s * PAIRS + pB];
    }

    float A0, A1, A2, A3;
    {
        float4 f0 = fa[0], f1 = fb[0];
        bool lo = (e < 2);
        float4 f = lo ? f0 : f1;
        float u = (e & 1) ? f.z : f.x;
        float v = (e & 1) ? f.w : f.y;
        A0 = lo ? u : 0.f;
        A1 = lo ? v : 0.f;
        A2 = lo ? 0.f : u;
        A3 = lo ? 0.f : v;
    }

    #pragma unroll
    for (int s = 1; s < DEPTH; s++) {
        float a00 = fa[s].x, a01 = fa[s].y, a10 = fa[s].z, a11 = fa[s].w;
        float b00 = fb[s].x, b01 = fb[s].y, b10 = fb[s].z, b11 = fb[s].w;
        float r0 = A0, r1 = A1, r2 = A2, r3 = A3;
        A0 = a00 * r0 + a10 * r2;
        A2 = a01 * r0 + a11 * r2;
        A1 = b00 * r1 + b10 * r3;
        A3 = b01 * r1 + b11 * r3;
    }

    g_C[t] = make_float4(A0, A1, A2, A3);
}

// ---------------------------------------------------------------------------
// Kernel 2: out[t, group g] = A_g * x[t, g] + bias_g (column-major A):
//   r = b + v.x*c0 + v.y*c1 + v.z*c2 + v.w*c3
// All 16 token loads issued before any compute/store: MLP_p1 = 16.
// ---------------------------------------------------------------------------
#define QUAD(rr, vv)                                                        \
    rr.x = b.x + vv.x*c0.x + vv.y*c1.x + vv.z*c2.x + vv.w*c3.x;             \
    rr.y = b.y + vv.x*c0.y + vv.y*c1.y + vv.z*c2.y + vv.w*c3.y;             \
    rr.z = b.z + vv.x*c0.z + vv.y*c1.z + vv.z*c2.z + vv.w*c3.z;             \
    rr.w = b.w + vv.x*c0.w + vv.y*c1.w + vv.z*c2.w + vv.w*c3.w;

__global__ void __launch_bounds__(256, 2)
butterfly_apply(const float4* __restrict__ x,
                const float4* __restrict__ bias4,
                float4* __restrict__ out) {
    int g  = blockIdx.x * blockDim.x + threadIdx.x;  // 0..GROUPS-1
    int t0 = blockIdx.y * T_PER;

    const float4* xp = x   + (size_t)t0 * GROUPS + g;
    float4*       op = out + (size_t)t0 * GROUPS + g;

    // ---- all 16 loads in flight before anything else (MLP_p1 = 16) ----
    float4 v0  = __ldcs(xp +  0 * GROUPS);
    float4 v1  = __ldcs(xp +  1 * GROUPS);
    float4 v2  = __ldcs(xp +  2 * GROUPS);
    float4 v3  = __ldcs(xp +  3 * GROUPS);
    float4 v4  = __ldcs(xp +  4 * GROUPS);
    float4 v5  = __ldcs(xp +  5 * GROUPS);
    float4 v6  = __ldcs(xp +  6 * GROUPS);
    float4 v7  = __ldcs(xp +  7 * GROUPS);
    float4 v8  = __ldcs(xp +  8 * GROUPS);
    float4 v9  = __ldcs(xp +  9 * GROUPS);
    float4 v10 = __ldcs(xp + 10 * GROUPS);
    float4 v11 = __ldcs(xp + 11 * GROUPS);
    float4 v12 = __ldcs(xp + 12 * GROUPS);
    float4 v13 = __ldcs(xp + 13 * GROUPS);
    float4 v14 = __ldcs(xp + 14 * GROUPS);
    float4 v15 = __ldcs(xp + 15 * GROUPS);

    float4 c0 = g_C[g * 4 + 0];
    float4 c1 = g_C[g * 4 + 1];
    float4 c2 = g_C[g * 4 + 2];
    float4 c3 = g_C[g * 4 + 3];
    float4 b  = bias4[g];

    float4 r0, r1, r2, r3;
    QUAD(r0, v0)  QUAD(r1, v1)  QUAD(r2, v2)  QUAD(r3, v3)
    __stcs(op +  0 * GROUPS, r0);
    __stcs(op +  1 * GROUPS, r1);
    __stcs(op +  2 * GROUPS, r2);
    __stcs(op +  3 * GROUPS, r3);

    QUAD(r0, v4)  QUAD(r1, v5)  QUAD(r2, v6)  QUAD(r3, v7)
    __stcs(op +  4 * GROUPS, r0);
    __stcs(op +  5 * GROUPS, r1);
    __stcs(op +  6 * GROUPS, r2);
    __stcs(op +  7 * GROUPS, r3);

    QUAD(r0, v8)  QUAD(r1, v9)  QUAD(r2, v10) QUAD(r3, v11)
    __stcs(op +  8 * GROUPS, r0);
    __stcs(op +  9 * GROUPS, r1);
    __stcs(op + 10 * GROUPS, r2);
    __stcs(op + 11 * GROUPS, r3);

    QUAD(r0, v12) QUAD(r1, v13) QUAD(r2, v14) QUAD(r3, v15)
    __stcs(op + 12 * GROUPS, r0);
    __stcs(op + 13 * GROUPS, r1);
    __stcs(op + 14 * GROUPS, r2);
    __stcs(op + 15 * GROUPS, r3);
}

// ---------------------------------------------------------------------------
extern "C" void kernel_launch(void* const* d_in, const int* in_sizes, int n_in,
                              void* d_out, int out_size) {
    const float* x = nullptr;
    const float* factors = nullptr;
    const float* bias = nullptr;
    for (int i = 0; i < n_in; i++) {
        if (in_sizes[i] == TOKENS * NCOLS)            x = (const float*)d_in[i];
        else if (in_sizes[i] == DEPTH * PAIRS * 4)    factors = (const float*)d_in[i];
        else if (in_sizes[i] == NCOLS)                bias = (const float*)d_in[i];
    }

    // Kernel 1: 4096 threads = 1 per (group, column).
    butterfly_precompute<<<32, 128>>>((const float4*)factors);

    // Kernel 2: (4, 512) = 2048 blocks, 16 tokens per thread.
    dim3 grid(GROUPS / 256, TOKENS / T_PER);
    butterfly_apply<<<grid, 256>>>((const float4*)x,
                                   (const float4*)bias,
                                   (float4*)d_out);
}